// round 2
// baseline (speedup 1.0000x reference)
#include <cuda_runtime.h>
#include <cuda_bf16.h>
#include <cstdint>

#define DIMN 512
#define MT   64
#define NROWS 65536
#define NCTAS (NROWS / MT)        // 1024
#define NTHREADS 512
#define ETA   0.1f
#define OMETA 0.9f

// smem layout: a-tile [64][512] bf16 swizzled (64KB) + two G k-slice buffers [32][512] bf16 (32KB each)
static constexpr uint32_t A_OFF  = 0;
static constexpr uint32_t G_OFF0 = 65536;
static constexpr uint32_t G_OFF1 = 98304;
static constexpr uint32_t SMEM_TOTAL = 131072;

// G' = -eta * (0.5*(G+G^T)) with zero diagonal, bf16, row-major [K=512][N=512]
__device__ __nv_bfloat16 g_gp[DIMN * DIMN];

__global__ void lca_prep_kernel(const float* __restrict__ G) {
    int idx = blockIdx.x * blockDim.x + threadIdx.x;   // 512*512 threads
    int i = idx >> 9, j = idx & 511;
    float v = (i == j) ? 0.0f : -ETA * 0.5f * (G[idx] + G[j * DIMN + i]);
    g_gp[idx] = __float2bfloat16(v);
}

__device__ __forceinline__ uint32_t smem_u32(const void* p) {
    uint32_t a;
    asm("{ .reg .u64 t; cvta.to.shared.u64 t, %1; cvt.u32.u64 %0, t; }" : "=r"(a) : "l"(p));
    return a;
}

__device__ __forceinline__ void ldsm4(uint32_t* r, uint32_t addr) {
    asm volatile("ldmatrix.sync.aligned.m8n8.x4.shared.b16 {%0,%1,%2,%3}, [%4];"
                 : "=r"(r[0]), "=r"(r[1]), "=r"(r[2]), "=r"(r[3]) : "r"(addr));
}
__device__ __forceinline__ void ldsm4t(uint32_t* r, uint32_t addr) {
    asm volatile("ldmatrix.sync.aligned.m8n8.x4.trans.shared.b16 {%0,%1,%2,%3}, [%4];"
                 : "=r"(r[0]), "=r"(r[1]), "=r"(r[2]), "=r"(r[3]) : "r"(addr));
}
__device__ __forceinline__ void mma_bf16(float* c, const uint32_t* a, uint32_t b0, uint32_t b1) {
    asm volatile("mma.sync.aligned.m16n8k16.row.col.f32.bf16.bf16.f32 "
                 "{%0,%1,%2,%3}, {%4,%5,%6,%7}, {%8,%9}, {%0,%1,%2,%3};"
                 : "+f"(c[0]), "+f"(c[1]), "+f"(c[2]), "+f"(c[3])
                 : "r"(a[0]), "r"(a[1]), "r"(a[2]), "r"(a[3]), "r"(b0), "r"(b1));
}
__device__ __forceinline__ void cp_async16(uint32_t dst, const void* src) {
    asm volatile("cp.async.cg.shared.global [%0], [%1], 16;" :: "r"(dst), "l"(src) : "memory");
}

__global__ __launch_bounds__(NTHREADS, 1)
void lca_main_kernel(const float* __restrict__ u,
                     const float* __restrict__ log_lam,
                     float* __restrict__ out) {
    extern __shared__ char smem[];
    const uint32_t sb = smem_u32(smem);
    const int tid  = threadIdx.x;
    const int lane = tid & 31;
    const int warp = tid >> 5;
    const int wm = warp >> 3;              // 0..1  (row group, 32 rows each)
    const int wn = warp & 7;               // 0..7  (col group, 64 cols each)
    const int m0 = wm * 32;
    const int n0 = wn * 64;
    const uint32_t un0 = (uint32_t)(n0 >> 3);
    const int grow0 = blockIdx.x * MT;
    const float lam = expf(log_lam[0]);

    const int r4 = lane >> 2;
    const int c2 = (lane & 3) * 2;

    // acc[fm][ni][4] : warp tile m32 x n64; fm = m16 half, ni = n8 frag
    float acc[2][8][4];

    // ---- ldmatrix lane-constant addresses ----
    // A: addr = A_OFF + r_l*1024 + ((K*2 ^ cb ^ s) << 4), r_l = m0 + fm*16 + (lane&15), s = lane&7, cb = lane>>4
    const uint32_t a_lrow0 = sb + A_OFF + (uint32_t)(m0 + (lane & 15)) * 1024u;
    const uint32_t a_lrow1 = a_lrow0 + 16u * 1024u;
    const uint32_t a_cbs = ((uint32_t)(lane >> 4)) ^ ((uint32_t)(lane & 7));
    // B: addr = buf + (h*16 + (lane&15))*1024 + (((un0 + 2p + (lane>>4)) ^ (lane&7)) << 4)
    const uint32_t b_rowoff = (uint32_t)(lane & 15) * 1024u;
    uint32_t b_pu[4];
#pragma unroll
    for (int p = 0; p < 4; p++)
        b_pu[p] = (((un0 + (uint32_t)(2 * p) + (uint32_t)(lane >> 4)) ^ (uint32_t)(lane & 7)) << 4);

    // ---- prefetch G chunk 0 into buf0 ----
    {
        const char* src = (const char*)g_gp + (size_t)tid * 16;
#pragma unroll
        for (int j = 0; j < 4; j++) {
            int q = tid + j * 512;
            int r = q >> 6, cu = q & 63;
            uint32_t dst = sb + G_OFF0 + (uint32_t)r * 1024u + ((uint32_t)(cu ^ (r & 7)) << 4);
            cp_async16(dst, src + j * 8192);
        }
        asm volatile("cp.async.commit_group;" ::: "memory");
    }

    // ---- init: v1 = eta*u; a1 = soft(v1) -> SMEM; acc = 0.9*v1 + 0.1*u ----
#pragma unroll
    for (int fm = 0; fm < 2; fm++)
#pragma unroll
    for (int rh = 0; rh < 2; rh++) {
        int rl = m0 + fm * 16 + rh * 8 + r4;
        const float* urow = u + (size_t)(grow0 + rl) * DIMN;
        uint32_t abase = sb + A_OFF + (uint32_t)rl * 1024u + (uint32_t)(c2 * 2);
        uint32_t sw = (uint32_t)(rl & 7);
#pragma unroll
        for (int ni = 0; ni < 8; ni++) {
            float2 uv = *(const float2*)(urow + n0 + ni * 8 + c2);
            float v0 = ETA * uv.x, v1 = ETA * uv.y;
            float s0 = fabsf(v0) - lam, s1 = fabsf(v1) - lam;
            float a0 = (s0 > 0.0f) ? copysignf(s0, v0) : 0.0f;
            float a1 = (s1 > 0.0f) ? copysignf(s1, v1) : 0.0f;
            __nv_bfloat162 h2 = __floats2bfloat162_rn(a0, a1);
            uint32_t aaddr = abase + (((un0 + (uint32_t)ni) ^ sw) << 4);
            asm volatile("st.shared.b32 [%0], %1;" :: "r"(aaddr), "r"(*(uint32_t*)&h2) : "memory");
            acc[fm][ni][rh * 2 + 0] = fmaf(OMETA, v0, ETA * uv.x);
            acc[fm][ni][rh * 2 + 1] = fmaf(OMETA, v1, ETA * uv.y);
        }
    }
    __syncthreads();

    // ---- 9 fused iterations ----
#pragma unroll 1
    for (int it = 0; it < 9; it++) {
#pragma unroll 1
        for (int kb = 0; kb < 16; kb++) {
            const uint32_t buf = sb + ((kb & 1) ? G_OFF1 : G_OFF0);
            const bool lastchunk = (it == 8) && (kb == 15);
            if (!lastchunk) {
                // prefetch next chunk (rows ((kb+1)&15)*32) into the other buffer
                int nkb = (kb + 1) & 15;
                uint32_t dstb = sb + (((kb + 1) & 1) ? G_OFF1 : G_OFF0);
                const char* src = (const char*)g_gp + (size_t)nkb * 32768 + (size_t)tid * 16;
#pragma unroll
                for (int j = 0; j < 4; j++) {
                    int q = tid + j * 512;
                    int r = q >> 6, cu = q & 63;
                    uint32_t dst = dstb + (uint32_t)r * 1024u + ((uint32_t)(cu ^ (r & 7)) << 4);
                    cp_async16(dst, src + j * 8192);
                }
                asm volatile("cp.async.commit_group;" ::: "memory");
                asm volatile("cp.async.wait_group 1;" ::: "memory");
            } else {
                asm volatile("cp.async.wait_group 0;" ::: "memory");
            }
            __syncthreads();

            // two k16 steps on this 32-row chunk
#pragma unroll
            for (int h = 0; h < 2; h++) {
                const int K = kb * 2 + h;           // global k16 index (0..31)
                uint32_t A0[4], A1[4];
                uint32_t aoff = (((uint32_t)(K << 1) ^ a_cbs) << 4);
                ldsm4(A0, a_lrow0 + aoff);
                ldsm4(A1, a_lrow1 + aoff);
                uint32_t brow = buf + b_rowoff + (uint32_t)(h * 16384);
                uint32_t B[4][4];
#pragma unroll
                for (int p = 0; p < 4; p++) ldsm4t(B[p], brow + b_pu[p]);
#pragma unroll
                for (int p = 0; p < 4; p++) {
                    mma_bf16(acc[0][2 * p + 0], A0, B[p][0], B[p][1]);
                    mma_bf16(acc[0][2 * p + 1], A0, B[p][2], B[p][3]);
                    mma_bf16(acc[1][2 * p + 0], A1, B[p][0], B[p][1]);
                    mma_bf16(acc[1][2 * p + 1], A1, B[p][2], B[p][3]);
                }
            }
            __syncthreads();
        }

        // ---- epilogue: acc now holds v_{t+1} ----
        if (it < 8) {
#pragma unroll
            for (int fm = 0; fm < 2; fm++)
#pragma unroll
            for (int rh = 0; rh < 2; rh++) {
                int rl = m0 + fm * 16 + rh * 8 + r4;
                const float* urow = u + (size_t)(grow0 + rl) * DIMN;
                uint32_t abase = sb + A_OFF + (uint32_t)rl * 1024u + (uint32_t)(c2 * 2);
                uint32_t sw = (uint32_t)(rl & 7);
#pragma unroll
                for (int ni = 0; ni < 8; ni++) {
                    float v0 = acc[fm][ni][rh * 2 + 0];
                    float v1 = acc[fm][ni][rh * 2 + 1];
                    float s0 = fabsf(v0) - lam, s1 = fabsf(v1) - lam;
                    float a0 = (s0 > 0.0f) ? copysignf(s0, v0) : 0.0f;
                    float a1 = (s1 > 0.0f) ? copysignf(s1, v1) : 0.0f;
                    __nv_bfloat162 h2 = __floats2bfloat162_rn(a0, a1);
                    uint32_t aaddr = abase + (((un0 + (uint32_t)ni) ^ sw) << 4);
                    asm volatile("st.shared.b32 [%0], %1;" :: "r"(aaddr), "r"(*(uint32_t*)&h2) : "memory");
                    float2 uv = *(const float2*)(urow + n0 + ni * 8 + c2);
                    acc[fm][ni][rh * 2 + 0] = fmaf(OMETA, v0, ETA * uv.x);
                    acc[fm][ni][rh * 2 + 1] = fmaf(OMETA, v1, ETA * uv.y);
                }
            }
            __syncthreads();
        } else {
            // final: a10 = soft(v10) -> out
#pragma unroll
            for (int fm = 0; fm < 2; fm++)
#pragma unroll
            for (int rh = 0; rh < 2; rh++) {
                int rl = m0 + fm * 16 + rh * 8 + r4;
                float* orow = out + (size_t)(grow0 + rl) * DIMN;
#pragma unroll
                for (int ni = 0; ni < 8; ni++) {
                    float v0 = acc[fm][ni][rh * 2 + 0];
                    float v1 = acc[fm][ni][rh * 2 + 1];
                    float s0 = fabsf(v0) - lam, s1 = fabsf(v1) - lam;
                    float2 o;
                    o.x = (s0 > 0.0f) ? copysignf(s0, v0) : 0.0f;
                    o.y = (s1 > 0.0f) ? copysignf(s1, v1) : 0.0f;
                    *(float2*)(orow + n0 + ni * 8 + c2) = o;
                }
            }
        }
    }
}

extern "C" void kernel_launch(void* const* d_in, const int* in_sizes, int n_in,
                              void* d_out, int out_size) {
    const float* u = nullptr;
    const float* G = nullptr;
    const float* ll = nullptr;
    for (int i = 0; i < n_in; i++) {
        if (in_sizes[i] == NROWS * DIMN)      u  = (const float*)d_in[i];
        else if (in_sizes[i] == DIMN * DIMN)  G  = (const float*)d_in[i];
        else                                  ll = (const float*)d_in[i];
    }
    float* out = (float*)d_out;

    lca_prep_kernel<<<DIMN, DIMN>>>(G);

    static bool attr_set = false;
    cudaFuncSetAttribute(lca_main_kernel,
                         cudaFuncAttributeMaxDynamicSharedMemorySize, SMEM_TOTAL);
    (void)attr_set;
    lca_main_kernel<<<NCTAS, NTHREADS, SMEM_TOTAL>>>(u, ll, out);
}